// round 3
// baseline (speedup 1.0000x reference)
#include <cuda_runtime.h>
#include <math.h>

#define DEPTH 24
#define DLAT 80
#define HEADS 8
#define DHD 64
#define INNER 512
#define FFD 160
#define BB 64
#define NNODE 128
#define ROWS (BB*NNODE)   // 8192
#define MHD 20

// ---------------- scratch (device globals; no runtime allocation) ----------------
__device__ float g_bias[BB*NNODE*NNODE];      // [64,128,128]
__device__ float g_x[ROWS*DLAT];              // residual stream
__device__ float g_h[ROWS*DLAT];              // post-LN
__device__ float g_qkv[ROWS*3*INNER];         // [8192,1536] : q | k | v
__device__ float g_o[ROWS*INNER];             // attention out [8192,512]
__device__ float g_u[ROWS*FFD];               // ffn hidden [8192,160]

// ---------------- bias: e + sp_bias ----------------
__global__ void bias_kernel(const int* __restrict__ sp_pos,
                            const int* __restrict__ edge_input,
                            const float* __restrict__ edge_emb,
                            const float* __restrict__ edge_dis_w,
                            const float* __restrict__ spatial_emb) {
    __shared__ float s_emb[64];
    __shared__ float s_w[MHD];
    __shared__ float s_sp[40];
    int t = threadIdx.x;
    if (t < 64) s_emb[t] = edge_emb[t];
    if (t < MHD) s_w[t] = edge_dis_w[t];
    if (t < 40) s_sp[t] = spatial_emb[t];
    __syncthreads();
    int idx = blockIdx.x * blockDim.x + t;
    if (idx >= BB*NNODE*NNODE) return;
    int spv = sp_pos[idx];
    int sp = (spv == 0) ? 1 : spv;
    sp = (sp > 1) ? (sp - 1) : sp;
    sp = (sp > MHD) ? MHD : sp;

    int buf[60];
    const int4* e4 = reinterpret_cast<const int4*>(edge_input + (size_t)idx * 60);
    #pragma unroll
    for (int m = 0; m < 15; m++) {
        int4 w = e4[m];
        buf[4*m+0] = w.x; buf[4*m+1] = w.y; buf[4*m+2] = w.z; buf[4*m+3] = w.w;
    }
    float acc = 0.f;
    #pragma unroll
    for (int hh = 0; hh < MHD; hh++) {
        float m = (s_emb[buf[3*hh]] + s_emb[buf[3*hh+1]] + s_emb[buf[3*hh+2]]) * (1.f/3.f);
        acc += m * s_w[hh];
    }
    g_bias[idx] = acc / (float)sp + s_sp[spv];
}

// ---------------- node embeddings ----------------
__global__ void embed_kernel(const int* __restrict__ x_nodes,
                             const int* __restrict__ indeg,
                             const int* __restrict__ outdeg,
                             const float* __restrict__ ae,
                             const float* __restrict__ ie,
                             const float* __restrict__ oe) {
    int row = blockIdx.x;
    int d = threadIdx.x;
    if (d < DLAT) {
        g_x[row*DLAT + d] = ae[x_nodes[row]*DLAT + d]
                          + ie[indeg[row]*DLAT + d]
                          + oe[outdeg[row]*DLAT + d];
    }
}

// ---------------- layernorm: g_x -> g_h ----------------
__global__ void ln_kernel(const float* __restrict__ gam, const float* __restrict__ bet) {
    int row = blockIdx.x * 8 + threadIdx.y;
    int lane = threadIdx.x;
    const float* xr = g_x + row*DLAT;
    float v0 = xr[lane];
    float v1 = xr[lane+32];
    float v2 = (lane < 16) ? xr[lane+64] : 0.f;
    float s = v0 + v1 + v2;
    #pragma unroll
    for (int o = 16; o; o >>= 1) s += __shfl_xor_sync(0xffffffffu, s, o);
    float mean = s * (1.f/80.f);
    float d0 = v0 - mean, d1 = v1 - mean, d2 = (lane < 16) ? (v2 - mean) : 0.f;
    float q = d0*d0 + d1*d1 + d2*d2;
    #pragma unroll
    for (int o = 16; o; o >>= 1) q += __shfl_xor_sync(0xffffffffu, q, o);
    float inv = rsqrtf(q * (1.f/80.f) + 1e-5f);
    float* hr = g_h + row*DLAT;
    hr[lane]    = d0*inv*gam[lane]    + bet[lane];
    hr[lane+32] = d1*inv*gam[lane+32] + bet[lane+32];
    if (lane < 16) hr[lane+64] = d2*inv*gam[lane+64] + bet[lane+64];
}

// ---------------- qkv gemm: g_h[8192,80] @ [Wq|Wkv][80,1536] -> g_qkv ----------------
__global__ void __launch_bounds__(128) gemm_qkv_kernel(const float* __restrict__ Wq,
                                                       const float* __restrict__ Wkv) {
    __shared__ float Hs[64*80];
    __shared__ float Ws[80*64];
    int m0 = blockIdx.x * 64;
    int n0 = blockIdx.y * 64;
    int t = threadIdx.x;
    for (int i = t; i < 64*20; i += 128) {
        int r = i / 20, c = i % 20;
        *(float4*)&Hs[r*80 + c*4] = *(const float4*)&g_h[(m0+r)*80 + c*4];
    }
    for (int i = t; i < 80*64; i += 128) {
        int k = i >> 6, c = i & 63;
        int n = n0 + c;
        Ws[i] = (n < INNER) ? Wq[k*INNER + n] : Wkv[k*(2*INNER) + (n - INNER)];
    }
    __syncthreads();
    int tx = t & 15, ty = t >> 4;
    float acc[8][4] = {};
    #pragma unroll 4
    for (int k = 0; k < 80; k++) {
        float4 w = *(const float4*)&Ws[(k << 6) + (tx << 2)];
        #pragma unroll
        for (int r = 0; r < 8; r++) {
            float a = Hs[(ty + (r << 3))*80 + k];
            acc[r][0] += a*w.x; acc[r][1] += a*w.y; acc[r][2] += a*w.z; acc[r][3] += a*w.w;
        }
    }
    #pragma unroll
    for (int r = 0; r < 8; r++) {
        float4 v = make_float4(acc[r][0], acc[r][1], acc[r][2], acc[r][3]);
        *(float4*)&g_qkv[(size_t)(m0 + ty + (r << 3))*1536 + n0 + (tx << 2)] = v;
    }
}

// ---------------- ffn1: g_h @ W1[80,160] + b1, gelu -> g_u ----------------
__global__ void __launch_bounds__(128) gemm_ffn1_kernel(const float* __restrict__ W1,
                                                        const float* __restrict__ b1) {
    __shared__ float Hs[64*80];
    __shared__ float Ws[80*64];
    int m0 = blockIdx.x * 64;
    int n0 = blockIdx.y * 64;
    int t = threadIdx.x;
    for (int i = t; i < 64*20; i += 128) {
        int r = i / 20, c = i % 20;
        *(float4*)&Hs[r*80 + c*4] = *(const float4*)&g_h[(m0+r)*80 + c*4];
    }
    for (int i = t; i < 80*64; i += 128) {
        int k = i >> 6;
        int n = n0 + (i & 63);
        Ws[i] = (n < FFD) ? W1[k*FFD + n] : 0.f;
    }
    __syncthreads();
    int tx = t & 15, ty = t >> 4;
    float acc[8][4] = {};
    #pragma unroll 4
    for (int k = 0; k < 80; k++) {
        float4 w = *(const float4*)&Ws[(k << 6) + (tx << 2)];
        #pragma unroll
        for (int r = 0; r < 8; r++) {
            float a = Hs[(ty + (r << 3))*80 + k];
            acc[r][0] += a*w.x; acc[r][1] += a*w.y; acc[r][2] += a*w.z; acc[r][3] += a*w.w;
        }
    }
    int ncol = n0 + (tx << 2);
    if (ncol < FFD) {
        #pragma unroll
        for (int r = 0; r < 8; r++) {
            float4 v;
            float vv;
            vv = acc[r][0] + b1[ncol+0]; v.x = vv*0.5f*(1.f + erff(vv*0.70710678118654752f));
            vv = acc[r][1] + b1[ncol+1]; v.y = vv*0.5f*(1.f + erff(vv*0.70710678118654752f));
            vv = acc[r][2] + b1[ncol+2]; v.z = vv*0.5f*(1.f + erff(vv*0.70710678118654752f));
            vv = acc[r][3] + b1[ncol+3]; v.w = vv*0.5f*(1.f + erff(vv*0.70710678118654752f));
            *(float4*)&g_u[(size_t)(m0 + ty + (r << 3))*FFD + ncol] = v;
        }
    }
}

// ---------------- A @ W[K,80] + bias + residual -> g_x (in place) ----------------
// mode 0: A = g_o (K=512, Wo);  mode 1: A = g_u (K=160, W2)
__global__ void __launch_bounds__(160) gemm_resid_kernel(const float* __restrict__ W,
                                                         const float* __restrict__ bias,
                                                         int mode) {
    __shared__ float As[64*33];
    __shared__ float Ws[32*80];
    const float* A = mode ? g_u : g_o;
    int K = mode ? FFD : INNER;
    int m0 = blockIdx.x * 64;
    int t = threadIdx.x;
    int tx = t % 20, ty = t / 20;
    float acc[8][4] = {};
    for (int k0 = 0; k0 < K; k0 += 32) {
        __syncthreads();
        for (int i = t; i < 64*32; i += 160) {
            int r = i >> 5, c = i & 31;
            As[r*33 + c] = A[(size_t)(m0 + r)*K + k0 + c];
        }
        for (int i = t; i < 32*80; i += 160) {
            Ws[i] = W[(size_t)(k0 + i/80)*80 + (i % 80)];
        }
        __syncthreads();
        #pragma unroll 4
        for (int kk = 0; kk < 32; kk++) {
            float4 w = *(const float4*)&Ws[kk*80 + (tx << 2)];
            #pragma unroll
            for (int r = 0; r < 8; r++) {
                float a = As[(ty + (r << 3))*33 + kk];
                acc[r][0] += a*w.x; acc[r][1] += a*w.y; acc[r][2] += a*w.z; acc[r][3] += a*w.w;
            }
        }
    }
    int col = tx << 2;
    float4 bsv = *(const float4*)&bias[col];
    #pragma unroll
    for (int r = 0; r < 8; r++) {
        int row = m0 + ty + (r << 3);
        float4 res = *(const float4*)&g_x[row*80 + col];
        float4 v = make_float4(acc[r][0] + bsv.x + res.x,
                               acc[r][1] + bsv.y + res.y,
                               acc[r][2] + bsv.z + res.z,
                               acc[r][3] + bsv.w + res.w);
        *(float4*)&g_x[row*80 + col] = v;
    }
}

// ---------------- attention: one block per (b, head) ----------------
// smem: Q[128][68], K[128][68], V[128][68], S[128][132]  = 172032 bytes (dynamic)
#define ATTN_SMEM ((3*128*68 + 128*132) * 4)
__global__ void __launch_bounds__(256) attn_kernel() {
    extern __shared__ float sm[];
    float* Qs = sm;
    float* Ks = Qs + 128*68;
    float* Vs = Ks + 128*68;
    float* Ss = Vs + 128*68;
    int bh = blockIdx.x;
    int b = bh >> 3, hh = bh & 7;
    int t = threadIdx.x;

    const float* qbase = g_qkv + (size_t)(b*NNODE)*1536 + hh*DHD;
    for (int i = t; i < 128*16; i += 256) {
        int r = i >> 4, c4 = i & 15;
        *(float4*)&Qs[r*68 + c4*4] = *(const float4*)(qbase + (size_t)r*1536 + c4*4);
        *(float4*)&Ks[r*68 + c4*4] = *(const float4*)(qbase + 512 + (size_t)r*1536 + c4*4);
        *(float4*)&Vs[r*68 + c4*4] = *(const float4*)(qbase + 1024 + (size_t)r*1536 + c4*4);
    }
    const float* bb = g_bias + (size_t)b*NNODE*NNODE;
    for (int i = t; i < 128*128; i += 256) {
        Ss[(i >> 7)*132 + (i & 127)] = bb[i];
    }
    __syncthreads();

    int tx = t & 15, ty = t >> 4;
    {
        float acc[8][8] = {};
        #pragma unroll 2
        for (int k = 0; k < 64; k++) {
            float a[8], kb[8];
            #pragma unroll
            for (int r = 0; r < 8; r++) a[r] = Qs[(ty + 16*r)*68 + k];
            #pragma unroll
            for (int c = 0; c < 8; c++) kb[c] = Ks[(tx + 16*c)*68 + k];
            #pragma unroll
            for (int r = 0; r < 8; r++)
                #pragma unroll
                for (int c = 0; c < 8; c++)
                    acc[r][c] += a[r]*kb[c];
        }
        #pragma unroll
        for (int r = 0; r < 8; r++)
            #pragma unroll
            for (int c = 0; c < 8; c++)
                Ss[(ty + 16*r)*132 + tx + 16*c] += acc[r][c]*0.125f;
    }
    __syncthreads();

    if (t < 128) {
        float* row = Ss + t*132;
        float mx = -1e30f;
        for (int j = 0; j < 128; j++) mx = fmaxf(mx, row[j]);
        float sum = 0.f;
        for (int j = 0; j < 128; j++) { float e = __expf(row[j] - mx); row[j] = e; sum += e; }
        float inv = 1.f / sum;
        for (int j = 0; j < 128; j++) row[j] *= inv;
    }
    __syncthreads();

    {
        float oacc[8][4] = {};
        #pragma unroll 2
        for (int j = 0; j < 128; j++) {
            float a[8], v[4];
            #pragma unroll
            for (int r = 0; r < 8; r++) a[r] = Ss[(ty + 16*r)*132 + j];
            #pragma unroll
            for (int c = 0; c < 4; c++) v[c] = Vs[j*68 + tx + 16*c];
            #pragma unroll
            for (int r = 0; r < 8; r++)
                #pragma unroll
                for (int c = 0; c < 4; c++)
                    oacc[r][c] += a[r]*v[c];
        }
        float* obase = g_o + (size_t)(b*NNODE)*INNER + hh*DHD;
        #pragma unroll
        for (int r = 0; r < 8; r++)
            #pragma unroll
            for (int c = 0; c < 4; c++)
                obase[(size_t)(ty + 16*r)*INNER + tx + 16*c] = oacc[r][c];
    }
}

// ---------------- final: pool, LN, linear ----------------
__global__ void final_kernel(const float* __restrict__ gam, const float* __restrict__ bet,
                             const float* __restrict__ Wf, const float* __restrict__ bf,
                             float* __restrict__ out) {
    __shared__ float p[DLAT];
    int b = blockIdx.x, d = threadIdx.x;
    if (d < DLAT) {
        float s = 0.f;
        for (int n = 0; n < NNODE; n++) s += g_x[(size_t)((b << 7) + n)*DLAT + d];
        p[d] = s * (1.f/128.f);
    }
    __syncthreads();
    if (d == 0) {
        float m = 0.f;
        for (int i = 0; i < DLAT; i++) m += p[i];
        m *= (1.f/80.f);
        float v = 0.f;
        for (int i = 0; i < DLAT; i++) { float dd = p[i] - m; v += dd*dd; }
        v *= (1.f/80.f);
        float inv = rsqrtf(v + 1e-5f);
        float acc = bf[0];
        for (int i = 0; i < DLAT; i++)
            acc += ((p[i] - m)*inv*gam[i] + bet[i]) * Wf[i];
        out[b] = acc;
    }
}

// ---------------- launcher ----------------
extern "C" void kernel_launch(void* const* d_in, const int* in_sizes, int n_in,
                              void* d_out, int out_size) {
    const int*   spatial_pos = (const int*)d_in[0];
    const int*   edge_input  = (const int*)d_in[1];
    const int*   x_nodes     = (const int*)d_in[2];
    const int*   indeg       = (const int*)d_in[3];
    const int*   outdeg      = (const int*)d_in[4];
    const float* atom_emb    = (const float*)d_in[5];
    const float* indeg_emb   = (const float*)d_in[6];
    const float* outdeg_emb  = (const float*)d_in[7];
    const float* edge_emb    = (const float*)d_in[8];
    const float* edge_dis_w  = (const float*)d_in[9];
    const float* spatial_emb = (const float*)d_in[10];
    const float* ln1_g = (const float*)d_in[11];
    const float* ln1_b = (const float*)d_in[12];
    const float* Wq    = (const float*)d_in[13];
    const float* Wkv   = (const float*)d_in[14];
    const float* Wo    = (const float*)d_in[15];
    const float* bo    = (const float*)d_in[16];
    const float* ln2_g = (const float*)d_in[17];
    const float* ln2_b = (const float*)d_in[18];
    const float* W1    = (const float*)d_in[19];
    const float* b1    = (const float*)d_in[20];
    const float* W2    = (const float*)d_in[21];
    const float* b2    = (const float*)d_in[22];
    const float* lnf_g = (const float*)d_in[23];
    const float* lnf_b = (const float*)d_in[24];
    const float* Wf    = (const float*)d_in[25];
    const float* bf    = (const float*)d_in[26];
    float* out = (float*)d_out;

    cudaFuncSetAttribute(attn_kernel, cudaFuncAttributeMaxDynamicSharedMemorySize, ATTN_SMEM);

    bias_kernel<<<(BB*NNODE*NNODE)/256, 256>>>(spatial_pos, edge_input, edge_emb,
                                               edge_dis_w, spatial_emb);
    embed_kernel<<<ROWS, 80>>>(x_nodes, indeg, outdeg, atom_emb, indeg_emb, outdeg_emb);

    for (int l = 0; l < DEPTH; l++) {
        ln_kernel<<<ROWS/8, dim3(32, 8)>>>(ln1_g + l*DLAT, ln1_b + l*DLAT);
        gemm_qkv_kernel<<<dim3(ROWS/64, 24), 128>>>(Wq + (size_t)l*DLAT*INNER,
                                                    Wkv + (size_t)l*DLAT*2*INNER);
        attn_kernel<<<BB*HEADS, 256, ATTN_SMEM>>>();
        gemm_resid_kernel<<<ROWS/64, 160>>>(Wo + (size_t)l*INNER*DLAT, bo + l*DLAT, 0);
        ln_kernel<<<ROWS/8, dim3(32, 8)>>>(ln2_g + l*DLAT, ln2_b + l*DLAT);
        gemm_ffn1_kernel<<<dim3(ROWS/64, 3), 128>>>(W1 + (size_t)l*DLAT*FFD, b1 + l*FFD);
        gemm_resid_kernel<<<ROWS/64, 160>>>(W2 + (size_t)l*FFD*DLAT, b2 + l*DLAT, 1);
    }
    final_kernel<<<BB, 80>>>(lnf_g, lnf_b, Wf, bf, out);
}